// round 16
// baseline (speedup 1.0000x reference)
#include <cuda_runtime.h>
#include <cuda_fp16.h>
#include <cstdint>

#define S_LEN 4096
#define EMB   1024
#define HALF  512
#define NHEAD 16
#define DH    32
#define SPLIT 2
#define KEYS_PER_SPLIT (S_LEN / SPLIT)

// f16 scratch
__device__ __half g_xh [S_LEN * HALF];   // x left half
__device__ __half g_wh [2560 * HALF];    // Wq|Wk|Wv|Wo rows (k-major)
__device__ __half g_qh [S_LEN * HALF];   // Q (scale*log2e folded in)
__device__ __half g_kh [S_LEN * HALF];
__device__ __half g_vh [S_LEN * HALF];
__device__ __half g_ath[S_LEN * HALF];   // normalized attention output (f16)

// split-K partials: O in packed f16x2, l in fp32
__device__ uint32_t g_po[SPLIT][S_LEN * HALF / 2];
__device__ float    g_pl[SPLIT][S_LEN * NHEAD];
__device__ int      g_ctr[(S_LEN / 128) * NHEAD];   // 512 arrival counters

__device__ __forceinline__ uint32_t packh2(float lo, float hi) {
    uint32_t r;
    asm("cvt.rn.f16x2.f32 %0, %1, %2;" : "=r"(r) : "f"(hi), "f"(lo));
    return r;
}
__device__ __forceinline__ float2 h2f2(uint32_t v) {
    __half2 h = *(__half2*)&v;
    return __half22float2(h);
}
__device__ __forceinline__ uint32_t ex2h2(uint32_t s) {
    uint32_t r;
    asm("ex2.approx.f16x2 %0, %1;" : "=r"(r) : "r"(s));
    return r;
}
__device__ __forceinline__ uint32_t smem_u32(const void* p) {
    uint32_t a;
    asm("{ .reg .u64 t; cvta.to.shared.u64 t, %1; cvt.u32.u64 %0, t; }" : "=r"(a) : "l"(p));
    return a;
}
__device__ __forceinline__ void mma_f16(float* d, const uint32_t* a, uint32_t b0, uint32_t b1) {
    asm volatile(
        "mma.sync.aligned.m16n8k16.row.col.f32.f16.f16.f32 "
        "{%0,%1,%2,%3}, {%4,%5,%6,%7}, {%8,%9}, {%0,%1,%2,%3};"
        : "+f"(d[0]), "+f"(d[1]), "+f"(d[2]), "+f"(d[3])
        : "r"(a[0]), "r"(a[1]), "r"(a[2]), "r"(a[3]), "r"(b0), "r"(b1));
}
__device__ __forceinline__ void ldsm4(uint32_t* r, uint32_t a) {
    asm volatile("ldmatrix.sync.aligned.m8n8.x4.shared.b16 {%0,%1,%2,%3}, [%4];"
        : "=r"(r[0]), "=r"(r[1]), "=r"(r[2]), "=r"(r[3]) : "r"(a));
}
__device__ __forceinline__ void ldsm4t(uint32_t* r, uint32_t a) {
    asm volatile("ldmatrix.sync.aligned.m8n8.x4.trans.shared.b16 {%0,%1,%2,%3}, [%4];"
        : "=r"(r[0]), "=r"(r[1]), "=r"(r[2]), "=r"(r[3]) : "r"(a));
}
__device__ __forceinline__ void cpa16(uint32_t dst, const void* src) {
    asm volatile("cp.async.cg.shared.global [%0], [%1], 16;" :: "r"(dst), "l"(src) : "memory");
}
#define CP_COMMIT() asm volatile("cp.async.commit_group;" ::: "memory")
#define CP_WAIT0()  asm volatile("cp.async.wait_group 0;" ::: "memory")

// ======================= merged conversion prologue ========================
// Also zeroes the split-K arrival counters (runs before attn every replay).
__global__ void __launch_bounds__(256) conv_all_kernel(
    const float* __restrict__ x,
    const float* __restrict__ Wq, const float* __restrict__ Wk,
    const float* __restrict__ Wv, const float* __restrict__ Wo)
{
    int idx = blockIdx.x * 256 + threadIdx.x;   // 0..425983
    if (idx < (S_LEN / 128) * NHEAD) g_ctr[idx] = 0;
    int r = idx >> 6;
    int c8 = (idx & 63) * 8;
    const float* src;
    __half* dst;
    if (r < 4096) {
        src = x + (size_t)r * EMB;
        dst = g_xh + (size_t)r * HALF;
    } else {
        int wr = r - 4096;
        if (wr < 512)       src = Wq + (size_t)wr * HALF;
        else if (wr < 1024) src = Wk + (size_t)(wr - 512) * HALF;
        else if (wr < 1536) src = Wv + (size_t)(wr - 1024) * HALF;
        else                src = Wo + (size_t)(wr - 1536) * HALF;
        dst = g_wh + (size_t)wr * HALF;
    }
    const float4 v0 = *(const float4*)&src[c8];
    const float4 v1 = *(const float4*)&src[c8 + 4];
    uint4 o;
    o.x = packh2(v0.x, v0.y); o.y = packh2(v0.z, v0.w);
    o.z = packh2(v1.x, v1.y); o.w = packh2(v1.z, v1.w);
    *(uint4*)&dst[c8] = o;
}

// ======================= f16 GEMM, CTA 128x128 =============================
// MODE 0: half2 out (scaled). MODE 3: float out + bias.
template <int MODE>
__device__ __forceinline__ void gemm_h(
    const __half* __restrict__ Ag, const __half* __restrict__ Bg,
    void* __restrict__ Cout, int ldc, const float* __restrict__ bias, float scale)
{
    __shared__ __align__(16) uint8_t sA[2][8192];
    __shared__ __align__(16) uint8_t sB[2][8192];

    const int t = threadIdx.x;
    const int lane = t & 31;
    const int w = t >> 5;
    const int wm = (w & 3) * 32;
    const int wn = (w >> 2) * 64;
    const int g = lane >> 2;
    const int c = lane & 3;
    const int grp = lane >> 3;
    const int m0 = blockIdx.x * 128;
    const int n0 = blockIdx.y * 128;

    const int arow0 = (lane & 7) + 8 * (grp & 1);
    const int ajb = grp >> 1;
    const int asw = (arow0 >> 1) & 3;
    const int brow0 = (lane & 7) + 8 * (grp >> 1);
    const int bjb = grp & 1;
    const int bsw = (brow0 >> 1) & 3;

    const int lr[2] = {t >> 2, (t + 256) >> 2};
    const int ac = t & 3;

    uint4 pa[2], pb[2];
#pragma unroll
    for (int i = 0; i < 2; i++) {
        pa[i] = *(const uint4*)((const uint8_t*)Ag + (size_t)(m0 + lr[i]) * 1024 + ac * 16);
        pb[i] = *(const uint4*)((const uint8_t*)Bg + (size_t)(n0 + lr[i]) * 1024 + ac * 16);
    }
    {
#pragma unroll
        for (int i = 0; i < 2; i++) {
            const int off = lr[i] * 64 + ((ac ^ ((lr[i] >> 1) & 3)) << 4);
            *(uint4*)(sA[0] + off) = pa[i];
            *(uint4*)(sB[0] + off) = pb[i];
        }
    }

    float acc[2][8][4] = {};

#pragma unroll 1
    for (int i = 0; i < 16; i++) {
        __syncthreads();
        const int b = i & 1;
        if (i < 15) {
            const int k0 = (i + 1) * 32;
#pragma unroll
            for (int j = 0; j < 2; j++) {
                pa[j] = *(const uint4*)((const uint8_t*)Ag + (size_t)(m0 + lr[j]) * 1024 + k0 * 2 + ac * 16);
                pb[j] = *(const uint4*)((const uint8_t*)Bg + (size_t)(n0 + lr[j]) * 1024 + k0 * 2 + ac * 16);
            }
        }
        const uint32_t abase = smem_u32(sA[b]);
        const uint32_t bbase = smem_u32(sB[b]);
#pragma unroll
        for (int kc = 0; kc < 2; kc++) {
            uint32_t av[2][4], bv[4][4];
#pragma unroll
            for (int mt = 0; mt < 2; mt++)
                ldsm4(av[mt], abase + (wm + mt * 16 + arow0) * 64 + (((2 * kc + ajb) ^ asw) << 4));
#pragma unroll
            for (int np = 0; np < 4; np++)
                ldsm4(bv[np], bbase + (wn + np * 16 + brow0) * 64 + (((2 * kc + bjb) ^ bsw) << 4));
#pragma unroll
            for (int mt = 0; mt < 2; mt++)
#pragma unroll
                for (int np = 0; np < 4; np++) {
                    mma_f16(acc[mt][2 * np], av[mt], bv[np][0], bv[np][1]);
                    mma_f16(acc[mt][2 * np + 1], av[mt], bv[np][2], bv[np][3]);
                }
        }
        if (i < 15) {
            uint8_t* dA = sA[b ^ 1];
            uint8_t* dB = sB[b ^ 1];
#pragma unroll
            for (int j = 0; j < 2; j++) {
                const int off = lr[j] * 64 + ((ac ^ ((lr[j] >> 1) & 3)) << 4);
                *(uint4*)(dA + off) = pa[j];
                *(uint4*)(dB + off) = pb[j];
            }
        }
    }

#pragma unroll
    for (int mt = 0; mt < 2; mt++) {
        const int r0 = m0 + wm + mt * 16 + g;
#pragma unroll
        for (int nt = 0; nt < 8; nt++) {
            const int col = n0 + wn + nt * 8 + 2 * c;
            const float* a = acc[mt][nt];
            if (MODE == 3) {
                float* C = (float*)Cout;
                const float b0 = bias[col], b1 = bias[col + 1];
                *(float2*)&C[(size_t)r0 * ldc + col] = make_float2(a[0] + b0, a[1] + b1);
                *(float2*)&C[(size_t)(r0 + 8) * ldc + col] = make_float2(a[2] + b0, a[3] + b1);
            } else {
                uint32_t* C = (uint32_t*)Cout;
                C[(size_t)r0 * (ldc / 2) + col / 2] = packh2(a[0] * scale, a[1] * scale);
                C[(size_t)(r0 + 8) * (ldc / 2) + col / 2] = packh2(a[2] * scale, a[3] * scale);
            }
        }
    }
}

__global__ void __launch_bounds__(256, 2) qkv_h_kernel()
{
    const int z = blockIdx.z;
    const float QS = 0.125f * 1.4426950408889634f;
    const __half* B = g_wh + (size_t)z * 512 * HALF;
    void* C = (z == 0) ? (void*)g_qh : (z == 1) ? (void*)g_kh : (void*)g_vh;
    gemm_h<0>(g_xh, B, C, HALF, nullptr, (z == 0) ? QS : 1.0f);
}

__global__ void __launch_bounds__(256, 2) proj_h_kernel(
    const float* __restrict__ bo, float* __restrict__ out)
{
    gemm_h<3>(g_ath, g_wh + (size_t)1536 * HALF, out, EMB, bo, 1.0f);
}

// ======================= flash attention (split-K=2, fused reduce) =========
// CTA = 128 q x 1 head x 1 key-split, 128 thr (4 warps x 32 q).
// Partials written f16; second-arriving CTA of each (q-block, head) pair
// performs the reduction (deterministic: fp add is commutative).
__global__ void __launch_bounds__(128, 5) attn_kernel()
{
    __shared__ __align__(16) uint8_t sK[2][8192];
    __shared__ __align__(16) uint8_t sV[2][8192];
    __shared__ int s_old;

    const int t = threadIdx.x;
    const int lane = t & 31;
    const int w = t >> 5;
    const int g = lane >> 2;
    const int c = lane & 3;
    const int grp = lane >> 3;
    const int h = blockIdx.y;
    const int z = blockIdx.z;
    const int q0 = blockIdx.x * 128 + w * 32;
    const size_t kb0 = (size_t)z * KEYS_PER_SPLIT;

    const int krow0 = (lane & 7) + 8 * (grp >> 1);
    const int kjb = grp & 1;
    const int ksw = (krow0 >> 1) & 3;
    const int vrow0 = (lane & 7) + 8 * (grp & 1);
    const int vjb = grp >> 1;
    const int vsw = (vrow0 >> 1) & 3;

    uint32_t qa[2][2][4];
#pragma unroll
    for (int mt = 0; mt < 2; mt++) {
        const uint32_t* r0p = (const uint32_t*)g_qh + (size_t)(q0 + mt * 16 + g) * 256 + h * 16;
        const uint32_t* r8p = r0p + 8 * 256;
#pragma unroll
        for (int kc = 0; kc < 2; kc++) {
            qa[mt][kc][0] = r0p[8 * kc + c];
            qa[mt][kc][1] = r8p[8 * kc + c];
            qa[mt][kc][2] = r0p[8 * kc + c + 4];
            qa[mt][kc][3] = r8p[8 * kc + c + 4];
        }
    }

    float o[2][4][4] = {};
    float lacc[2][4] = {};
    const uint32_t ONE2 = 0x3C003C00u;

    const uint8_t* Kh = (const uint8_t*)(g_kh + h * DH);
    const uint8_t* Vh = (const uint8_t*)(g_vh + h * DH);

    const uint32_t skb[2] = {smem_u32(sK[0]), smem_u32(sK[1])};
    const uint32_t svb[2] = {smem_u32(sV[0]), smem_u32(sV[1])};
    int soff[4], goff[4];
#pragma unroll
    for (int i = 0; i < 4; i++) {
        const int slot = t + i * 128;
        const int r = slot >> 2, cc = slot & 3;
        soff[i] = r * 64 + ((cc ^ ((r >> 1) & 3)) << 4);
        goff[i] = r * 1024 + cc * 16;
    }

#pragma unroll
    for (int i = 0; i < 4; i++) {
        cpa16(skb[0] + soff[i], Kh + kb0 * 1024 + goff[i]);
        cpa16(svb[0] + soff[i], Vh + kb0 * 1024 + goff[i]);
    }
    CP_COMMIT();

    const int NT = KEYS_PER_SPLIT / 128;
#pragma unroll 1
    for (int ti = 0; ti < NT; ti++) {
        const int b = ti & 1;
        CP_WAIT0();
        __syncthreads();
        if (ti + 1 < NT) {
            const size_t base = (kb0 + (size_t)(ti + 1) * 128) * 1024;
#pragma unroll
            for (int i = 0; i < 4; i++) {
                cpa16(skb[b ^ 1] + soff[i], Kh + base + goff[i]);
                cpa16(svb[b ^ 1] + soff[i], Vh + base + goff[i]);
            }
            CP_COMMIT();
        }

        const uint32_t kbase = skb[b];
        const uint32_t vbase = svb[b];

#pragma unroll
        for (int kk = 0; kk < 8; kk++) {
            const int roff = kk * 16;
            uint32_t kv0[4], kv1[4];
            const uint32_t krow = kbase + (roff + krow0) * 64;
            ldsm4(kv0, krow + (((0 + kjb) ^ ksw) << 4));
            ldsm4(kv1, krow + (((2 + kjb) ^ ksw) << 4));

            float s[2][2][4] = {};
#pragma unroll
            for (int mt = 0; mt < 2; mt++) {
                mma_f16(s[mt][0], qa[mt][0], kv0[0], kv0[1]);
                mma_f16(s[mt][1], qa[mt][0], kv0[2], kv0[3]);
                mma_f16(s[mt][0], qa[mt][1], kv1[0], kv1[1]);
                mma_f16(s[mt][1], qa[mt][1], kv1[2], kv1[3]);
            }

            uint32_t v0[4], v1[4];
            const uint32_t vrow = vbase + (roff + vrow0) * 64;
            ldsm4t(v0, vrow + (((0 + vjb) ^ vsw) << 4));
            ldsm4t(v1, vrow + (((2 + vjb) ^ vsw) << 4));

#pragma unroll
            for (int mt = 0; mt < 2; mt++) {
                uint32_t a[4];
                a[0] = ex2h2(packh2(s[mt][0][0], s[mt][0][1]));
                a[1] = ex2h2(packh2(s[mt][0][2], s[mt][0][3]));
                a[2] = ex2h2(packh2(s[mt][1][0], s[mt][1][1]));
                a[3] = ex2h2(packh2(s[mt][1][2], s[mt][1][3]));
                mma_f16(o[mt][0], a, v0[0], v0[1]);
                mma_f16(o[mt][1], a, v0[2], v0[3]);
                mma_f16(o[mt][2], a, v1[0], v1[1]);
                mma_f16(o[mt][3], a, v1[2], v1[3]);
                mma_f16(lacc[mt], a, ONE2, ONE2);
            }
        }
    }

    // write packed f16 partials (unnormalized) + fp32 l
    uint32_t* po = g_po[z];
    float* pl = g_pl[z];
#pragma unroll
    for (int mt = 0; mt < 2; mt++) {
        const int r0 = q0 + mt * 16 + g;
#pragma unroll
        for (int nt = 0; nt < 4; nt++) {
            const int cw = h * 16 + nt * 4 + c;     // uint32 col index
            po[(size_t)r0 * 256 + cw] = packh2(o[mt][nt][0], o[mt][nt][1]);
            po[(size_t)(r0 + 8) * 256 + cw] = packh2(o[mt][nt][2], o[mt][nt][3]);
        }
        if (c == 0) {
            pl[(size_t)r0 * NHEAD + h] = lacc[mt][0];
            pl[(size_t)(r0 + 8) * NHEAD + h] = lacc[mt][2];
        }
    }

    // ---- fused split-K reduce: second-arriving CTA normalizes ----
    __threadfence();                        // publish partials (release)
    __syncthreads();                        // all threads' writes done
    if (t == 0)
        s_old = atomicAdd(&g_ctr[blockIdx.x * NHEAD + h], 1);
    __syncthreads();
    if (s_old == 1) {
        __threadfence();                    // acquire other CTA's writes
        const int r = blockIdx.x * 128 + t; // one row per thread
        const float l = g_pl[0][(size_t)r * NHEAD + h] + g_pl[1][(size_t)r * NHEAD + h];
        const float inv = 1.0f / l;
        const size_t base = (size_t)r * 256 + h * 16;
#pragma unroll
        for (int j = 0; j < 4; j++) {
            const uint4 A = *(const uint4*)&g_po[0][base + j * 4];
            const uint4 B = *(const uint4*)&g_po[1][base + j * 4];
            float2 a0 = h2f2(A.x), b0 = h2f2(B.x);
            float2 a1 = h2f2(A.y), b1 = h2f2(B.y);
            float2 a2 = h2f2(A.z), b2 = h2f2(B.z);
            float2 a3 = h2f2(A.w), b3 = h2f2(B.w);
            uint4 oo;
            oo.x = packh2((a0.x + b0.x) * inv, (a0.y + b0.y) * inv);
            oo.y = packh2((a1.x + b1.x) * inv, (a1.y + b1.y) * inv);
            oo.z = packh2((a2.x + b2.x) * inv, (a2.y + b2.y) * inv);
            oo.w = packh2((a3.x + b3.x) * inv, (a3.y + b3.y) * inv);
            *(uint4*)((uint32_t*)g_ath + base + j * 4) = oo;
        }
    }
}

extern "C" void kernel_launch(void* const* d_in, const int* in_sizes, int n_in,
                              void* d_out, int out_size)
{
    const float* x  = (const float*)d_in[0];
    const float* Wq = (const float*)d_in[1];
    const float* Wk = (const float*)d_in[2];
    const float* Wv = (const float*)d_in[3];
    const float* Wo = (const float*)d_in[4];
    const float* bo = (const float*)d_in[5];
    float* out = (float*)d_out;

    conv_all_kernel<<<1664, 256>>>(x, Wq, Wk, Wv, Wo);

    dim3 gq(S_LEN / 128, HALF / 128, 3);     // (32, 4, 3) = 384 CTAs
    qkv_h_kernel<<<gq, 256>>>();

    dim3 ga(S_LEN / 128, NHEAD, SPLIT);      // (32, 16, 2) = 1024 CTAs
    attn_kernel<<<ga, 128>>>();

    dim3 gp(S_LEN / 128, EMB / 128);         // (32, 8) = 256 CTAs
    proj_h_kernel<<<gp, 256>>>(bo, out);
}

// round 17
// speedup vs baseline: 1.0824x; 1.0824x over previous
#include <cuda_runtime.h>
#include <cuda_fp16.h>
#include <cstdint>

#define S_LEN 4096
#define EMB   1024
#define HALF  512
#define NHEAD 16
#define DH    32
#define SPLIT 2
#define KEYS_PER_SPLIT (S_LEN / SPLIT)

// f16 scratch
__device__ __half g_xh [S_LEN * HALF];   // x left half
__device__ __half g_wh [2560 * HALF];    // Wq|Wk|Wv|Wo rows (k-major)
__device__ __half g_qh [S_LEN * HALF];   // Q (scale*log2e folded in)
__device__ __half g_kh [S_LEN * HALF];
__device__ __half g_vh [S_LEN * HALF];
__device__ __half g_ath[S_LEN * HALF];   // normalized attention output (f16)

// split-K partials: O in packed f16x2, l in fp32
__device__ uint32_t g_po[SPLIT][S_LEN * HALF / 2];
__device__ float    g_pl[SPLIT][S_LEN * NHEAD];

__device__ __forceinline__ uint32_t packh2(float lo, float hi) {
    uint32_t r;
    asm("cvt.rn.f16x2.f32 %0, %1, %2;" : "=r"(r) : "f"(hi), "f"(lo));
    return r;
}
__device__ __forceinline__ float2 h2f2(uint32_t v) {
    __half2 h = *(__half2*)&v;
    return __half22float2(h);
}
__device__ __forceinline__ uint32_t ex2h2(uint32_t s) {
    uint32_t r;
    asm("ex2.approx.f16x2 %0, %1;" : "=r"(r) : "r"(s));
    return r;
}
__device__ __forceinline__ uint32_t smem_u32(const void* p) {
    uint32_t a;
    asm("{ .reg .u64 t; cvta.to.shared.u64 t, %1; cvt.u32.u64 %0, t; }" : "=r"(a) : "l"(p));
    return a;
}
__device__ __forceinline__ void mma_f16(float* d, const uint32_t* a, uint32_t b0, uint32_t b1) {
    asm volatile(
        "mma.sync.aligned.m16n8k16.row.col.f32.f16.f16.f32 "
        "{%0,%1,%2,%3}, {%4,%5,%6,%7}, {%8,%9}, {%0,%1,%2,%3};"
        : "+f"(d[0]), "+f"(d[1]), "+f"(d[2]), "+f"(d[3])
        : "r"(a[0]), "r"(a[1]), "r"(a[2]), "r"(a[3]), "r"(b0), "r"(b1));
}
__device__ __forceinline__ void ldsm4(uint32_t* r, uint32_t a) {
    asm volatile("ldmatrix.sync.aligned.m8n8.x4.shared.b16 {%0,%1,%2,%3}, [%4];"
        : "=r"(r[0]), "=r"(r[1]), "=r"(r[2]), "=r"(r[3]) : "r"(a));
}
__device__ __forceinline__ void ldsm4t(uint32_t* r, uint32_t a) {
    asm volatile("ldmatrix.sync.aligned.m8n8.x4.trans.shared.b16 {%0,%1,%2,%3}, [%4];"
        : "=r"(r[0]), "=r"(r[1]), "=r"(r[2]), "=r"(r[3]) : "r"(a));
}
__device__ __forceinline__ void cpa16(uint32_t dst, const void* src) {
    asm volatile("cp.async.cg.shared.global [%0], [%1], 16;" :: "r"(dst), "l"(src) : "memory");
}
#define CP_COMMIT() asm volatile("cp.async.commit_group;" ::: "memory")
#define CP_WAIT0()  asm volatile("cp.async.wait_group 0;" ::: "memory")

// ======================= merged conversion prologue ========================
__global__ void __launch_bounds__(256) conv_all_kernel(
    const float* __restrict__ x,
    const float* __restrict__ Wq, const float* __restrict__ Wk,
    const float* __restrict__ Wv, const float* __restrict__ Wo)
{
    int idx = blockIdx.x * 256 + threadIdx.x;   // 0..425983
    int r = idx >> 6;
    int c8 = (idx & 63) * 8;
    const float* src;
    __half* dst;
    if (r < 4096) {
        src = x + (size_t)r * EMB;
        dst = g_xh + (size_t)r * HALF;
    } else {
        int wr = r - 4096;
        if (wr < 512)       src = Wq + (size_t)wr * HALF;
        else if (wr < 1024) src = Wk + (size_t)(wr - 512) * HALF;
        else if (wr < 1536) src = Wv + (size_t)(wr - 1024) * HALF;
        else                src = Wo + (size_t)(wr - 1536) * HALF;
        dst = g_wh + (size_t)wr * HALF;
    }
    const float4 v0 = *(const float4*)&src[c8];
    const float4 v1 = *(const float4*)&src[c8 + 4];
    uint4 o;
    o.x = packh2(v0.x, v0.y); o.y = packh2(v0.z, v0.w);
    o.z = packh2(v1.x, v1.y); o.w = packh2(v1.z, v1.w);
    *(uint4*)&dst[c8] = o;
}

// ======================= f16 GEMM, CTA 128x128, BK=64, cp.async ============
// C[m][n] = sum_k A[m][k]*B[n][k]. 256 thr (8 warps), warp tile 32x64.
// Tile = two 32-k subtiles (64B swizzled rows). Double-buffered via cp.async.
// Dynamic smem: 65536 B. MODE 0: half2 out (scaled). MODE 3: float + bias.
template <int MODE>
__device__ __forceinline__ void gemm_h(
    const __half* __restrict__ Ag, const __half* __restrict__ Bg,
    void* __restrict__ Cout, int ldc, const float* __restrict__ bias, float scale)
{
    extern __shared__ __align__(16) uint8_t dsm[];

    const int t = threadIdx.x;
    const int lane = t & 31;
    const int w = t >> 5;
    const int wm = (w & 3) * 32;
    const int wn = (w >> 2) * 64;
    const int g = lane >> 2;
    const int c = lane & 3;
    const int grp = lane >> 3;
    const int m0 = blockIdx.x * 128;
    const int n0 = blockIdx.y * 128;

    const int arow0 = (lane & 7) + 8 * (grp & 1);
    const int ajb = grp >> 1;
    const int asw = (arow0 >> 1) & 3;
    const int brow0 = (lane & 7) + 8 * (grp >> 1);
    const int bjb = grp & 1;
    const int bsw = (brow0 >> 1) & 3;

    // loader: 1024 16B-slots per matrix per tile; 4 per thread.
    // slot: sub = slot>>9 (k-subtile), r = (slot&511)>>2, cc = slot&3
    int soff[4];      // smem offset within matrix region
    int gofs[4];      // gmem byte offset within row (excl. k-iter base)
    int grow[4];      // row index
#pragma unroll
    for (int i = 0; i < 4; i++) {
        const int slot = t + i * 256;
        const int sub = slot >> 9;
        const int r = (slot & 511) >> 2;
        const int cc = slot & 3;
        soff[i] = sub * 8192 + r * 64 + ((cc ^ ((r >> 1) & 3)) << 4);
        gofs[i] = sub * 64 + cc * 16;
        grow[i] = r;
    }

    const uint32_t sbase = smem_u32(dsm);
    // buffer b: A at b*32768, B at b*32768 + 16384

    // prologue: load tile 0 into buf 0
#pragma unroll
    for (int i = 0; i < 4; i++) {
        cpa16(sbase + soff[i],
              (const uint8_t*)Ag + (size_t)(m0 + grow[i]) * 1024 + gofs[i]);
        cpa16(sbase + 16384 + soff[i],
              (const uint8_t*)Bg + (size_t)(n0 + grow[i]) * 1024 + gofs[i]);
    }
    CP_COMMIT();

    float acc[2][8][4] = {};
    const int NT = 8;   // 512 / 64

#pragma unroll 1
    for (int it = 0; it < NT; it++) {
        const int b = it & 1;
        CP_WAIT0();
        __syncthreads();
        if (it + 1 < NT) {
            const int kb = (it + 1) * 128;   // byte offset of k-iter
            const uint32_t nb = sbase + (b ^ 1) * 32768;
#pragma unroll
            for (int i = 0; i < 4; i++) {
                cpa16(nb + soff[i],
                      (const uint8_t*)Ag + (size_t)(m0 + grow[i]) * 1024 + kb + gofs[i]);
                cpa16(nb + 16384 + soff[i],
                      (const uint8_t*)Bg + (size_t)(n0 + grow[i]) * 1024 + kb + gofs[i]);
            }
            CP_COMMIT();
        }

        const uint32_t abase = sbase + b * 32768;
        const uint32_t bbase = abase + 16384;
#pragma unroll
        for (int kc = 0; kc < 4; kc++) {
            const int sub = kc >> 1;
            const int kin = kc & 1;
            uint32_t av[2][4], bv[4][4];
#pragma unroll
            for (int mt = 0; mt < 2; mt++)
                ldsm4(av[mt], abase + sub * 8192 + (wm + mt * 16 + arow0) * 64
                              + (((2 * kin + ajb) ^ asw) << 4));
#pragma unroll
            for (int np = 0; np < 4; np++)
                ldsm4(bv[np], bbase + sub * 8192 + (wn + np * 16 + brow0) * 64
                              + (((2 * kin + bjb) ^ bsw) << 4));
#pragma unroll
            for (int mt = 0; mt < 2; mt++)
#pragma unroll
                for (int np = 0; np < 4; np++) {
                    mma_f16(acc[mt][2 * np], av[mt], bv[np][0], bv[np][1]);
                    mma_f16(acc[mt][2 * np + 1], av[mt], bv[np][2], bv[np][3]);
                }
        }
    }

#pragma unroll
    for (int mt = 0; mt < 2; mt++) {
        const int r0 = m0 + wm + mt * 16 + g;
#pragma unroll
        for (int nt = 0; nt < 8; nt++) {
            const int col = n0 + wn + nt * 8 + 2 * c;
            const float* a = acc[mt][nt];
            if (MODE == 3) {
                float* C = (float*)Cout;
                const float b0 = bias[col], b1 = bias[col + 1];
                *(float2*)&C[(size_t)r0 * ldc + col] = make_float2(a[0] + b0, a[1] + b1);
                *(float2*)&C[(size_t)(r0 + 8) * ldc + col] = make_float2(a[2] + b0, a[3] + b1);
            } else {
                uint32_t* C = (uint32_t*)Cout;
                C[(size_t)r0 * (ldc / 2) + col / 2] = packh2(a[0] * scale, a[1] * scale);
                C[(size_t)(r0 + 8) * (ldc / 2) + col / 2] = packh2(a[2] * scale, a[3] * scale);
            }
        }
    }
}

__global__ void __launch_bounds__(256, 2) qkv_h_kernel()
{
    const int z = blockIdx.z;
    const float QS = 0.125f * 1.4426950408889634f;
    const __half* B = g_wh + (size_t)z * 512 * HALF;
    void* C = (z == 0) ? (void*)g_qh : (z == 1) ? (void*)g_kh : (void*)g_vh;
    gemm_h<0>(g_xh, B, C, HALF, nullptr, (z == 0) ? QS : 1.0f);
}

__global__ void __launch_bounds__(256, 2) proj_h_kernel(
    const float* __restrict__ bo, float* __restrict__ out)
{
    gemm_h<3>(g_ath, g_wh + (size_t)1536 * HALF, out, EMB, bo, 1.0f);
}

// ======================= flash attention (split-K=2, cp.async) =============
// CTA = 128 q x 1 head x 1 key-split, 128 thr (4 warps x 32 q).
// Partial O written as packed f16x2; l fp32.
__global__ void __launch_bounds__(128, 5) attn_kernel()
{
    __shared__ __align__(16) uint8_t sK[2][8192];
    __shared__ __align__(16) uint8_t sV[2][8192];

    const int t = threadIdx.x;
    const int lane = t & 31;
    const int w = t >> 5;
    const int g = lane >> 2;
    const int c = lane & 3;
    const int grp = lane >> 3;
    const int h = blockIdx.y;
    const int z = blockIdx.z;
    const int q0 = blockIdx.x * 128 + w * 32;
    const size_t kb0 = (size_t)z * KEYS_PER_SPLIT;

    const int krow0 = (lane & 7) + 8 * (grp >> 1);
    const int kjb = grp & 1;
    const int ksw = (krow0 >> 1) & 3;
    const int vrow0 = (lane & 7) + 8 * (grp & 1);
    const int vjb = grp >> 1;
    const int vsw = (vrow0 >> 1) & 3;

    uint32_t qa[2][2][4];
#pragma unroll
    for (int mt = 0; mt < 2; mt++) {
        const uint32_t* r0p = (const uint32_t*)g_qh + (size_t)(q0 + mt * 16 + g) * 256 + h * 16;
        const uint32_t* r8p = r0p + 8 * 256;
#pragma unroll
        for (int kc = 0; kc < 2; kc++) {
            qa[mt][kc][0] = r0p[8 * kc + c];
            qa[mt][kc][1] = r8p[8 * kc + c];
            qa[mt][kc][2] = r0p[8 * kc + c + 4];
            qa[mt][kc][3] = r8p[8 * kc + c + 4];
        }
    }

    float o[2][4][4] = {};
    float lacc[2][4] = {};
    const uint32_t ONE2 = 0x3C003C00u;

    const uint8_t* Kh = (const uint8_t*)(g_kh + h * DH);
    const uint8_t* Vh = (const uint8_t*)(g_vh + h * DH);

    const uint32_t skb[2] = {smem_u32(sK[0]), smem_u32(sK[1])};
    const uint32_t svb[2] = {smem_u32(sV[0]), smem_u32(sV[1])};
    int soff[4], goff[4];
#pragma unroll
    for (int i = 0; i < 4; i++) {
        const int slot = t + i * 128;
        const int r = slot >> 2, cc = slot & 3;
        soff[i] = r * 64 + ((cc ^ ((r >> 1) & 3)) << 4);
        goff[i] = r * 1024 + cc * 16;
    }

#pragma unroll
    for (int i = 0; i < 4; i++) {
        cpa16(skb[0] + soff[i], Kh + kb0 * 1024 + goff[i]);
        cpa16(svb[0] + soff[i], Vh + kb0 * 1024 + goff[i]);
    }
    CP_COMMIT();

    const int NT = KEYS_PER_SPLIT / 128;
#pragma unroll 1
    for (int ti = 0; ti < NT; ti++) {
        const int b = ti & 1;
        CP_WAIT0();
        __syncthreads();
        if (ti + 1 < NT) {
            const size_t base = (kb0 + (size_t)(ti + 1) * 128) * 1024;
#pragma unroll
            for (int i = 0; i < 4; i++) {
                cpa16(skb[b ^ 1] + soff[i], Kh + base + goff[i]);
                cpa16(svb[b ^ 1] + soff[i], Vh + base + goff[i]);
            }
            CP_COMMIT();
        }

        const uint32_t kbase = skb[b];
        const uint32_t vbase = svb[b];

#pragma unroll
        for (int kk = 0; kk < 8; kk++) {
            const int roff = kk * 16;
            uint32_t kv0[4], kv1[4];
            const uint32_t krow = kbase + (roff + krow0) * 64;
            ldsm4(kv0, krow + (((0 + kjb) ^ ksw) << 4));
            ldsm4(kv1, krow + (((2 + kjb) ^ ksw) << 4));

            float s[2][2][4] = {};
#pragma unroll
            for (int mt = 0; mt < 2; mt++) {
                mma_f16(s[mt][0], qa[mt][0], kv0[0], kv0[1]);
                mma_f16(s[mt][1], qa[mt][0], kv0[2], kv0[3]);
                mma_f16(s[mt][0], qa[mt][1], kv1[0], kv1[1]);
                mma_f16(s[mt][1], qa[mt][1], kv1[2], kv1[3]);
            }

            uint32_t v0[4], v1[4];
            const uint32_t vrow = vbase + (roff + vrow0) * 64;
            ldsm4t(v0, vrow + (((0 + vjb) ^ vsw) << 4));
            ldsm4t(v1, vrow + (((2 + vjb) ^ vsw) << 4));

#pragma unroll
            for (int mt = 0; mt < 2; mt++) {
                uint32_t a[4];
                a[0] = ex2h2(packh2(s[mt][0][0], s[mt][0][1]));
                a[1] = ex2h2(packh2(s[mt][0][2], s[mt][0][3]));
                a[2] = ex2h2(packh2(s[mt][1][0], s[mt][1][1]));
                a[3] = ex2h2(packh2(s[mt][1][2], s[mt][1][3]));
                mma_f16(o[mt][0], a, v0[0], v0[1]);
                mma_f16(o[mt][1], a, v0[2], v0[3]);
                mma_f16(o[mt][2], a, v1[0], v1[1]);
                mma_f16(o[mt][3], a, v1[2], v1[3]);
                mma_f16(lacc[mt], a, ONE2, ONE2);
            }
        }
    }

    uint32_t* po = g_po[z];
    float* pl = g_pl[z];
#pragma unroll
    for (int mt = 0; mt < 2; mt++) {
        const int r0 = q0 + mt * 16 + g;
#pragma unroll
        for (int nt = 0; nt < 4; nt++) {
            const int cw = h * 16 + nt * 4 + c;
            po[(size_t)r0 * 256 + cw] = packh2(o[mt][nt][0], o[mt][nt][1]);
            po[(size_t)(r0 + 8) * 256 + cw] = packh2(o[mt][nt][2], o[mt][nt][3]);
        }
        if (c == 0) {
            pl[(size_t)r0 * NHEAD + h] = lacc[mt][0];
            pl[(size_t)(r0 + 8) * NHEAD + h] = lacc[mt][2];
        }
    }
}

// ======================= split-K reduce ====================================
__global__ void __launch_bounds__(256) attn_reduce_kernel()
{
    const int idx = blockIdx.x * 256 + threadIdx.x;  // 262144 total
    const int r = idx >> 6;
    const int q = idx & 63;
    const int h = q >> 2;

    const float l = g_pl[0][(size_t)r * NHEAD + h] + g_pl[1][(size_t)r * NHEAD + h];
    const float inv = 1.0f / l;

    const uint4 A = *(const uint4*)&g_po[0][(size_t)r * 256 + q * 4];
    const uint4 B = *(const uint4*)&g_po[1][(size_t)r * 256 + q * 4];

    uint4 o;
    {
        float2 a0 = h2f2(A.x), b0 = h2f2(B.x);
        float2 a1 = h2f2(A.y), b1 = h2f2(B.y);
        float2 a2 = h2f2(A.z), b2 = h2f2(B.z);
        float2 a3 = h2f2(A.w), b3 = h2f2(B.w);
        o.x = packh2((a0.x + b0.x) * inv, (a0.y + b0.y) * inv);
        o.y = packh2((a1.x + b1.x) * inv, (a1.y + b1.y) * inv);
        o.z = packh2((a2.x + b2.x) * inv, (a2.y + b2.y) * inv);
        o.w = packh2((a3.x + b3.x) * inv, (a3.y + b3.y) * inv);
    }
    *(uint4*)((uint32_t*)g_ath + (size_t)r * 256 + q * 4) = o;
}

extern "C" void kernel_launch(void* const* d_in, const int* in_sizes, int n_in,
                              void* d_out, int out_size)
{
    const float* x  = (const float*)d_in[0];
    const float* Wq = (const float*)d_in[1];
    const float* Wk = (const float*)d_in[2];
    const float* Wv = (const float*)d_in[3];
    const float* Wo = (const float*)d_in[4];
    const float* bo = (const float*)d_in[5];
    float* out = (float*)d_out;

    const int GEMM_SMEM = 65536;
    static int attr_done = 0;
    if (!attr_done) {
        cudaFuncSetAttribute(qkv_h_kernel,
                             cudaFuncAttributeMaxDynamicSharedMemorySize, GEMM_SMEM);
        cudaFuncSetAttribute(proj_h_kernel,
                             cudaFuncAttributeMaxDynamicSharedMemorySize, GEMM_SMEM);
        attr_done = 1;
    }

    conv_all_kernel<<<1664, 256>>>(x, Wq, Wk, Wv, Wo);

    dim3 gq(S_LEN / 128, HALF / 128, 3);     // (32, 4, 3) = 384 CTAs
    qkv_h_kernel<<<gq, 256, GEMM_SMEM>>>();

    dim3 ga(S_LEN / 128, NHEAD, SPLIT);      // (32, 16, 2) = 1024 CTAs
    attn_kernel<<<ga, 128>>>();

    attn_reduce_kernel<<<1024, 256>>>();

    dim3 gp(S_LEN / 128, EMB / 128);         // (32, 8) = 256 CTAs
    proj_h_kernel<<<gp, 256, GEMM_SMEM>>>(bo, out);
}